// round 4
// baseline (speedup 1.0000x reference)
#include <cuda_runtime.h>
#include <math.h>

#define NPTS 64     // NUM_POINTS
#define NCF  32     // NUM_COEFF
#define NB   30     // NUM_COEFF - 2
#define NITER 20
#define NPROB (256*512)
#define PI_D 3.14159265358979323846

// ===================== compile-time constant tables =========================
// G, C, V, P0, P1, TC1 are independent of t_span (pure Chebyshev-grid math).
// Computed in fp64 at COMPILE TIME so they become FFMA immediates in SASS
// (imm-form FFMA has rt_SMSP=1 vs 2 for 3-reg, and needs no LDS).

struct Tbl {
    float G[NPTS][NB];   // G[k][m] = T[m+2](tch_k) - P0[m] - P1[m]*tch_k
    float C[NPTS][NB];   // Phi_c^T
    float V[NB];         // colsum of C
    float P0[NB], P1[NB];
    float TC1[NPTS];     // 1 + tch[k]
};

constexpr double ccos(double x) {            // Taylor, |x| <= pi, full fp64 acc
    double x2 = x * x, term = 1.0, s = 1.0;
    for (int n = 1; n <= 25; n++) { term *= -x2 / ((2.0*n - 1.0) * (2.0*n)); s += term; }
    return s;
}

constexpr Tbl make_tbl() {
    Tbl R{};
    double tch[NPTS] = {}, Dt[NPTS] = {};
    for (int k = 0; k < NPTS; k++) tch[k] = -ccos(PI_D * (double)k / (double)NPTS);
    for (int k = 0; k < NPTS; k++) {
        double tn = (k == NPTS-1) ? 1.0 : tch[k+1];
        Dt[k] = tn - tch[k];
    }
    double T[NCF][NPTS] = {}, DT[NCF][NPTS] = {};
    for (int k = 0; k < NPTS; k++) {
        double t = tch[k];
        T[0][k] = 1.0; T[1][k] = t;
        for (int n = 2; n < NCF; n++) T[n][k] = 2.0*t*T[n-1][k] - T[n-2][k];
        double Ua = 1.0, Ub = 2.0*t;
        DT[0][k] = 0.0; DT[1][k] = 1.0; DT[2][k] = 2.0*Ub;
        for (int n = 3; n < NCF; n++) {
            double Uc = 2.0*t*Ub - Ua;
            DT[n][k] = (double)n * Uc;
            Ua = Ub; Ub = Uc;
        }
    }
    double P0[NB] = {}, P1[NB] = {};
    for (int m = 0; m < NB; m++) { double d0 = DT[m+2][0]; P1[m] = d0; P0[m] = T[m+2][0] + d0; }
    double Gb[NB][NPTS] = {};
    for (int m = 0; m < NB; m++)
        for (int k = 0; k < NPTS; k++) Gb[m][k] = DT[m+2][k] - P1[m];
    // A = Gb*diag(Dt)*Gb^T ; invert via Gauss-Jordan with partial pivoting
    double M[NB][2*NB] = {};
    for (int i = 0; i < NB; i++)
        for (int j = 0; j < NB; j++) {
            double s = 0.0;
            for (int k = 0; k < NPTS; k++) s += Gb[i][k]*Dt[k]*Gb[j][k];
            M[i][j] = s;
            M[i][NB+j] = (i == j) ? 1.0 : 0.0;
        }
    for (int col = 0; col < NB; col++) {
        int p = col; double best = M[col][col] < 0 ? -M[col][col] : M[col][col];
        for (int r = col+1; r < NB; r++) {
            double v = M[r][col] < 0 ? -M[r][col] : M[r][col];
            if (v > best) { best = v; p = r; }
        }
        if (p != col)
            for (int c = 0; c < 2*NB; c++) { double tmp = M[col][c]; M[col][c] = M[p][c]; M[p][c] = tmp; }
        double piv = M[col][col];
        for (int c = 0; c < 2*NB; c++) M[col][c] /= piv;
        for (int r = 0; r < NB; r++) if (r != col) {
            double f = M[r][col];
            for (int c = 0; c < 2*NB; c++) M[r][c] -= f * M[col][c];
        }
    }
    double Cd[NPTS][NB] = {};
    for (int k = 0; k < NPTS; k++)
        for (int m = 0; m < NB; m++) {
            double s = 0.0;
            for (int j = 0; j < NB; j++) s += Gb[j][k] * M[j][NB+m];
            Cd[k][m] = Dt[k] * s;
        }
    for (int k = 0; k < NPTS; k++)
        for (int m = 0; m < NB; m++) {
            R.G[k][m] = (float)(T[m+2][k] - P0[m] - P1[m]*tch[k]);
            R.C[k][m] = (float)Cd[k][m];
        }
    for (int m = 0; m < NB; m++) {
        double v = 0.0;
        for (int k = 0; k < NPTS; k++) v += Cd[k][m];
        R.V[m] = (float)v; R.P0[m] = (float)P0[m]; R.P1[m] = (float)P1[m];
    }
    for (int k = 0; k < NPTS; k++) R.TC1[k] = (float)(1.0 + tch[k]);
    return R;
}

constexpr Tbl TB = make_tbl();

// ===================== runtime tables (depend on t_span) ====================
__device__ float c_sin[NPTS];       // sin(t_true[k])
__device__ float c_PO[NCF][16];     // Phi_out[c][t]
__device__ float c_scal[2];         // inv_s = (t1-t0)/2 , sin(t0)

__global__ void setup_kernel(const float* __restrict__ tspan) {
    int tid = threadIdx.x;
    double t0 = (double)tspan[0];
    double t1 = (double)tspan[15];
    double inv_s = 0.5 * (t1 - t0);
    if (tid < NPTS) {
        double tch = -cos(PI_D * (double)tid / (double)NPTS);
        c_sin[tid] = (float)sin(t0 + inv_s * (tch + 1.0));
    }
    if (tid == 0) { c_scal[0] = (float)inv_s; c_scal[1] = (float)sin(t0); }
    if (tid >= 64 && tid < 80) {
        int t = tid - 64;
        double tq = -1.0 + 2.0*((double)tspan[t] - t0)/(t1 - t0);
        double Tm2 = 1.0, Tm1 = tq;
        c_PO[0][t] = 1.0f; c_PO[1][t] = (float)tq;
        #pragma unroll 1
        for (int n = 2; n < NCF; n++) {
            double Tn = 2.0*tq*Tm1 - Tm2; c_PO[n][t] = (float)Tn; Tm2 = Tm1; Tm1 = Tn;
        }
    }
}

// ===================== main solve kernel ====================================
__device__ __forceinline__ float fast_tanh(float x) {
    float ax = fabsf(x);
    float e  = __expf(-2.0f * ax);                 // MUFU.EX2 path
    float t  = __fdividef(1.0f - e, 1.0f + e);     // MUFU.RCP path
    return copysignf(t, x);
}

// ---- template chains: constants become FFMA immediates ----
template<int K, int M>
__device__ __forceinline__ float dotG(const float (&B)[NB], float acc) {
    if constexpr (M >= NB) { return acc; }
    else {
        constexpr float g = TB.G[K][M];
        return dotG<K, M+4>(B, fmaf(B[M], g, acc));
    }
}

template<int K, int M>
__device__ __forceinline__ void accC(float (&acc)[NB], float f) {
    if constexpr (M < NB) {
        constexpr float c = TB.C[K][M];
        acc[M] = fmaf(f, c, acc[M]);
        accC<K, M+1>(acc, f);
    }
}

template<int K>
__device__ __forceinline__ void kstep(const float (&B)[NB], float (&acc)[NB],
                                      float y, float w, float aj,
                                      const float* __restrict__ sSin) {
    constexpr float tc1 = TB.TC1[K];
    float p0 = dotG<K, 0>(B, fmaf(w, tc1, y));
    float p1 = dotG<K, 1>(B, 0.f);
    float p2 = dotG<K, 2>(B, 0.f);
    float p3 = dotG<K, 3>(B, 0.f);
    float ya = (p0 + p1) + (p2 + p3);
    float f  = sSin[K] - fast_tanh(ya * aj);
    accC<K, 0>(acc, f);
}

template<int K>
__device__ __forceinline__ void kloop(const float (&B)[NB], float (&acc)[NB],
                                      float y, float w, float aj,
                                      const float* __restrict__ sSin) {
    if constexpr (K < NPTS) {
        kstep<K>(B, acc, y, w, aj, sSin);
        kloop<K+1>(B, acc, y, w, aj, sSin);
    }
}

template<int M>
__device__ __forceinline__ void updB(float (&B)[NB], const float (&acc)[NB],
                                     float invs, float w) {
    if constexpr (M < NB) {
        constexpr float v = TB.V[M];
        B[M] = fmaf(invs, acc[M], -(w * v));
        updB<M+1>(B, acc, invs, w);
    }
}

template<int M>
__device__ __forceinline__ float dotP0(const float (&B)[NB], float acc) {
    if constexpr (M >= NB) { return acc; }
    else { constexpr float p = -TB.P0[M]; return dotP0<M+1>(B, fmaf(B[M], p, acc)); }
}
template<int M>
__device__ __forceinline__ float dotP1(const float (&B)[NB], float acc) {
    if constexpr (M >= NB) { return acc; }
    else { constexpr float p = -TB.P1[M]; return dotP1<M+1>(B, fmaf(B[M], p, acc)); }
}

__global__ void __launch_bounds__(128, 5) solve_kernel(
    const float* __restrict__ y_init, const float* __restrict__ Bin,
    const float* __restrict__ a, float* __restrict__ out)
{
    __shared__ float sSin[NPTS];
    __shared__ float sPO[NCF][16];
    __shared__ float sScal[2];

    int tid = threadIdx.x;
    if (tid < NPTS) sSin[tid] = c_sin[tid];
    for (int e = tid; e < NCF*16; e += 128) (&sPO[0][0])[e] = (&c_PO[0][0])[e];
    if (tid < 2) sScal[tid] = c_scal[tid];
    __syncthreads();

    int idx  = blockIdx.x * 128 + tid;
    float y  = y_init[idx];
    float aj = a[idx & 511];
    float invs = sScal[0];
    float f0 = sScal[1] - fast_tanh(y * aj);
    float w  = f0 * invs;            // f0 / s

    float B[NB];
    #pragma unroll
    for (int m = 0; m < NB; m++) B[m] = Bin[idx*NB + m];

    #pragma unroll 1
    for (int it = 0; it < NITER; it++) {
        float acc[NB];
        #pragma unroll
        for (int m = 0; m < NB; m++) acc[m] = 0.f;
        kloop<0>(B, acc, y, w, aj, sSin);
        updB<0>(B, acc, invs, w);
    }

    // head = yf@inv0 - B@P   (P0/P1 are compile-time immediates)
    float h0 = dotP0<0>(B, y + w);
    float h1 = dotP1<0>(B, w);

    // B_full: (256,512,32) after the approx block
    float* outB = out + 16*NPROB;
    int b = idx * NCF;
    outB[b]   = h0;
    outB[b+1] = h1;
    #pragma unroll
    for (int m = 0; m < NB; m++) outB[b+2+m] = B[m];

    // approx: (16,256,512), coalesced over idx
    #pragma unroll
    for (int t = 0; t < 16; t++) {
        float val = fmaf(h0, sPO[0][t], h1 * sPO[1][t]);
        #pragma unroll
        for (int m = 0; m < NB; m++) val = fmaf(B[m], sPO[m+2][t], val);
        out[t*NPROB + idx] = val;
    }
}

// ===================== launch ===============================================
extern "C" void kernel_launch(void* const* d_in, const int* in_sizes, int n_in,
                              void* d_out, int out_size) {
    const float* y_init = (const float*)d_in[0];
    const float* B_init = (const float*)d_in[1];
    const float* t_span = (const float*)d_in[2];
    const float* a      = (const float*)d_in[3];
    float* out = (float*)d_out;
    setup_kernel<<<1, 128>>>(t_span);
    solve_kernel<<<NPROB/128, 128>>>(y_init, B_init, a, out);
}